// round 15
// baseline (speedup 1.0000x reference)
#include <cuda_runtime.h>
#include <cuda_fp16.h>
#include <cstdint>

#define BB 4
#define NN 4096
#define NSAMP 1024
#define KNB 32
#define MTOT (BB*NSAMP*KNB)   // 131072 positions

// ---------------- scratch (device globals; no allocations allowed) ------------
__device__ float g_w21[256*6];
__device__ int   g_knn[MTOT];
__device__ __half g_y1h[(size_t)MTOT*256];     // conv1 out RAW fp16, [m][c]
__device__ float g_xm[256*BB*NSAMP];           // [c][bs]
__device__ float g_h3[512*BB*NSAMP];           // [row][bs]
__device__ __half g_y3h[(size_t)MTOT*512];     // conv3 out RAW fp16, [n][512]
__device__ float g_y4m[256*BB*NSAMP];          // max_k of RAW y4, [c][bs]
__device__ __half g_w3bh[512*256];
__device__ __half g_w4h[256*512];
__device__ float g_sum2[256], g_sq2[256];
__device__ float g_sum3[512], g_sq3[512];
__device__ float g_sum4[256], g_sq4[256];
__device__ float g_s2[256], g_t2[256];
__device__ float g_s3[512], g_t3[512];
__device__ float g_s4[256], g_t4[256];

// ---------------- helpers -----------------------------------------------------
__device__ __forceinline__ uint32_t smem_to_u32(const void* p) {
    uint32_t a;
    asm("{ .reg .u64 t; cvta.to.shared.u64 t, %1; cvt.u32.u64 %0, t; }" : "=r"(a) : "l"(p));
    return a;
}
__device__ __forceinline__ unsigned long long dup2(float a) {
    unsigned int u = __float_as_uint(a);
    return ((unsigned long long)u << 32) | (unsigned long long)u;
}
__device__ __forceinline__ unsigned long long pk64(float a, float b) {
    unsigned long long r;
    asm("mov.b64 %0, {%1,%2};" : "=l"(r) : "f"(a), "f"(b));
    return r;
}
__device__ __forceinline__ void up64(float& a, float& b, unsigned long long v) {
    asm("mov.b64 {%0,%1}, %2;" : "=f"(a), "=f"(b) : "l"(v));
}
__device__ __forceinline__ unsigned long long fma2(unsigned long long a,
                                                   unsigned long long b,
                                                   unsigned long long c) {
    unsigned long long r;
    asm("fma.rn.f32x2 %0, %1, %2, %3;" : "=l"(r) : "l"(a), "l"(b), "l"(c));
    return r;
}
__device__ __forceinline__ unsigned int fmono(float f) {
    unsigned int u = __float_as_uint(f);
    return (u & 0x80000000u) ? ~u : (u | 0x80000000u);
}
__device__ __forceinline__ uint32_t pk2h(__half a, __half b) {
    return ((uint32_t)__half_as_ushort(b) << 16) | (uint32_t)__half_as_ushort(a);
}

#define CP_ASYNC16(dst, src) \
    asm volatile("cp.async.cg.shared.global [%0], [%1], 16;" :: "r"(dst), "l"(src) : "memory")
#define CP_COMMIT() asm volatile("cp.async.commit_group;" ::: "memory")
#define CP_WAIT0() asm volatile("cp.async.wait_group 0;" ::: "memory")
#define CP_WAIT1() asm volatile("cp.async.wait_group 1;" ::: "memory")

__device__ __forceinline__ void ldsm_x4(uint32_t& r0, uint32_t& r1, uint32_t& r2, uint32_t& r3, uint32_t addr) {
    asm volatile("ldmatrix.sync.aligned.m8n8.x4.shared.b16 {%0,%1,%2,%3}, [%4];"
        : "=r"(r0), "=r"(r1), "=r"(r2), "=r"(r3) : "r"(addr));
}
__device__ __forceinline__ void ldsm_x2(uint32_t& r0, uint32_t& r1, uint32_t addr) {
    asm volatile("ldmatrix.sync.aligned.m8n8.x2.shared.b16 {%0,%1}, [%2];"
        : "=r"(r0), "=r"(r1) : "r"(addr));
}
__device__ __forceinline__ void mma16816(float* d, const uint32_t* a, const uint32_t* b) {
    asm volatile("mma.sync.aligned.m16n8k16.row.col.f32.f16.f16.f32 "
        "{%0,%1,%2,%3}, {%4,%5,%6,%7}, {%8,%9}, {%0,%1,%2,%3};"
        : "+f"(d[0]), "+f"(d[1]), "+f"(d[2]), "+f"(d[3])
        : "r"(a[0]), "r"(a[1]), "r"(a[2]), "r"(a[3]), "r"(b[0]), "r"(b[1]));
}

// ---------------- zero stats --------------------------------------------------
__global__ void k_zero() {
    int t = threadIdx.x;  // 512
    if (t < 256) { g_sum2[t]=0.f; g_sq2[t]=0.f; g_sum4[t]=0.f; g_sq4[t]=0.f; }
    g_sum3[t]=0.f; g_sq3[t]=0.f;
}

// ---------------- w21 = w2 @ w1 -----------------------------------------------
__global__ void k_w21(const float* __restrict__ w1, const float* __restrict__ w2) {
    int o = threadIdx.x;
    float acc[6] = {0.f,0.f,0.f,0.f,0.f,0.f};
    for (int c = 0; c < 256; ++c) {
        float w = w2[o*256 + c];
        #pragma unroll
        for (int i = 0; i < 6; ++i) acc[i] = fmaf(w, w1[c*6+i], acc[i]);
    }
    #pragma unroll
    for (int i = 0; i < 6; ++i) g_w21[o*6+i] = acc[i];
}

// ---------------- weight fp16 -------------------------------------------------
__global__ void k_wsplit(const float* __restrict__ w3, const float* __restrict__ w4) {
    int i = blockIdx.x*256 + threadIdx.x;   // 0..131071
    int r = i >> 8, c = i & 255;
    g_w3bh[i] = __float2half(w3[r*512 + 256 + c]);
    g_w4h[i]  = __float2half(w4[i]);
}

// ---------------- FPS: 512 thr x 8 pts, single barrier/iter -------------------
__global__ void __launch_bounds__(512, 1) k_fps(const float* __restrict__ p,
                                                float* __restrict__ outC) {
    int b = blockIdx.x;
    const float* pb = p + b*NN*3;
    int t = threadIdx.x;
    int lane = t & 31, w = t >> 5;        // 16 warps

    float dm[8];
    unsigned long long pX[4], pY[4], pZ[4];
    #pragma unroll
    for (int j = 0; j < 4; ++j) {
        int i0 = t + (2*j)*512, i1 = t + (2*j+1)*512;
        pX[j] = pk64(pb[i0*3],   pb[i1*3]);
        pY[j] = pk64(pb[i0*3+1], pb[i1*3+1]);
        pZ[j] = pk64(pb[i0*3+2], pb[i1*3+2]);
        dm[2*j] = 1e10f; dm[2*j+1] = 1e10f;
    }
    const unsigned long long NEG1 = dup2(-1.0f);

    __shared__ unsigned s_v[2][16];
    __shared__ unsigned s_i[2][16];

    float cx = pb[0], cy = pb[1], cz = pb[2];
    if (t == 0) {
        float* o = outC + b*NSAMP*3;
        o[0] = cx; o[1] = cy; o[2] = cz;
    }

    for (int it = 0; it < NSAMP; ++it) {
        int buf = it & 1;
        unsigned long long c2x = dup2(cx), c2y = dup2(cy), c2z = dup2(cz);
        #pragma unroll
        for (int j = 0; j < 4; ++j) {
            unsigned long long tx = fma2(c2x, NEG1, pX[j]);
            unsigned long long ty = fma2(c2y, NEG1, pY[j]);
            unsigned long long tz = fma2(c2z, NEG1, pZ[j]);
            unsigned long long d2 = fma2(tx, tx, 0ull);
            d2 = fma2(ty, ty, d2);
            d2 = fma2(tz, tz, d2);
            float da, db; up64(da, db, d2);
            dm[2*j]   = fminf(dm[2*j],   da);
            dm[2*j+1] = fminf(dm[2*j+1], db);
        }

        float best = dm[0];
        #pragma unroll
        for (int j = 1; j < 8; ++j) best = fmaxf(best, dm[j]);
        int bi = t + 7*512;
        #pragma unroll
        for (int j = 6; j >= 0; --j) if (dm[j] == best) bi = t + j*512;

        unsigned mv   = fmono(best);
        unsigned wmax = __reduce_max_sync(0xffffffffu, mv);
        unsigned cand = (mv == wmax) ? (unsigned)bi : 0xffffffffu;
        unsigned widx = __reduce_min_sync(0xffffffffu, cand);
        if (lane == 0) { s_v[buf][w] = wmax; s_i[buf][w] = widx; }
        __syncthreads();

        unsigned mv2 = (lane < 16) ? s_v[buf][lane] : 0u;
        unsigned id2 = (lane < 16) ? s_i[buf][lane] : 0xffffffffu;
        unsigned m2  = __reduce_max_sync(0xffffffffu, mv2);
        unsigned c2v = (mv2 == m2) ? id2 : 0xffffffffu;
        unsigned far = __reduce_min_sync(0xffffffffu, c2v);

        cx = pb[far*3]; cy = pb[far*3+1]; cz = pb[far*3+2];
        if (t == 0 && it + 1 < NSAMP) {
            float* o = outC + (b*NSAMP + it + 1)*3;
            o[0] = cx; o[1] = cy; o[2] = cz;
        }
    }
}

// ---------------- KNN: 4-chain scan + 2-phase redux, 1 barrier/round ----------
__global__ void k_knn(const float* __restrict__ p, const float* __restrict__ cent) {
    int cid = blockIdx.x;
    int b = cid >> 10;
    const float* pb = p + b*NN*3;
    int t = threadIdx.x;  // 128
    int w = t >> 5, lane = t & 31;
    float cx = cent[cid*3], cy = cent[cid*3+1], cz = cent[cid*3+2];
    float cn = cx*cx + cy*cy + cz*cz;
    unsigned long long key[32];
    #pragma unroll
    for (int j = 0; j < 32; ++j) {
        int i = j*128 + t;
        float x = pb[i*3], y = pb[i*3+1], z = pb[i*3+2];
        float pn = x*x + y*y + z*z;
        float dot = fmaf(cx, x, fmaf(cy, y, cz*z));
        float d2  = fmaf(-2.0f, dot, cn + pn);
        key[j] = ((unsigned long long)fmono(d2) << 32) | (unsigned int)i;
    }

    __shared__ unsigned s_h[2][4], s_l[2][4];
    unsigned long long prev = 0ull;

    for (int r = 0; r < KNB; ++r) {
        int rb = r & 1;
        unsigned long long b0 = ~0ull, b1 = ~0ull, b2 = ~0ull, b3 = ~0ull;
        #pragma unroll
        for (int j = 0; j < 8; ++j) {
            unsigned long long k0 = key[j];
            if (k0 > prev && k0 < b0) b0 = k0;
            unsigned long long k1 = key[8 + j];
            if (k1 > prev && k1 < b1) b1 = k1;
            unsigned long long k2 = key[16 + j];
            if (k2 > prev && k2 < b2) b2 = k2;
            unsigned long long k3 = key[24 + j];
            if (k3 > prev && k3 < b3) b3 = k3;
        }
        if (b1 < b0) b0 = b1;
        if (b3 < b2) b2 = b3;
        unsigned long long best = (b2 < b0) ? b2 : b0;

        unsigned bh = (unsigned)(best >> 32), bl = (unsigned)best;
        unsigned mh = __reduce_min_sync(0xffffffffu, bh);
        unsigned cl = (bh == mh) ? bl : 0xffffffffu;
        unsigned ml = __reduce_min_sync(0xffffffffu, cl);
        if (lane == 0) { s_h[rb][w] = mh; s_l[rb][w] = ml; }
        __syncthreads();

        unsigned fh = s_h[rb][0], fl = s_l[rb][0];
        #pragma unroll
        for (int i = 1; i < 4; ++i) {
            unsigned hh = s_h[rb][i], ll = s_l[rb][i];
            if (hh < fh || (hh == fh && ll < fl)) { fh = hh; fl = ll; }
        }
        prev = ((unsigned long long)fh << 32) | fl;
        if (t == 0) g_knn[cid*KNB + r] = (int)fl;
    }
}

// ------- gather + conv(6->256)+bias -> y1h RAW fp16 [m][256] + stats2 ---------
__global__ void k_gconv1(const float* __restrict__ p, const float* __restrict__ f,
                         const float* __restrict__ b2) {
    __shared__ float sw[256*6];
    __shared__ float sbb[256];
    __shared__ float sv[64][6];
    int t = threadIdx.x;
    #pragma unroll
    for (int i = 0; i < 6; ++i) sw[t*6+i] = g_w21[t*6+i];
    sbb[t] = b2[t];
    int m0 = blockIdx.x*64;
    if (t < 64) {
        int m = m0 + t;
        int b = m >> 15;
        int idx = g_knn[m];
        const float* pp = p + b*NN*3 + idx*3;
        const float* ff = f + b*3*NN + idx;
        sv[t][0] = pp[0]; sv[t][1] = pp[1]; sv[t][2] = pp[2];
        sv[t][3] = ff[0]; sv[t][4] = ff[NN]; sv[t][5] = ff[2*NN];
    }
    __syncthreads();
    int c = t;
    float w0 = sw[c*6], w1 = sw[c*6+1], w2 = sw[c*6+2];
    float w3 = sw[c*6+3], w4 = sw[c*6+4], w5 = sw[c*6+5];
    float bias = sbb[c];
    float s = 0.f, q = 0.f;
    #pragma unroll 4
    for (int pp = 0; pp < 64; ++pp) {
        float a = bias;
        a = fmaf(w0, sv[pp][0], a); a = fmaf(w1, sv[pp][1], a); a = fmaf(w2, sv[pp][2], a);
        a = fmaf(w3, sv[pp][3], a); a = fmaf(w4, sv[pp][4], a); a = fmaf(w5, sv[pp][5], a);
        g_y1h[(size_t)(m0+pp)*256 + c] = __float2half(a);
        s += a; q = fmaf(a, a, q);
    }
    atomicAdd(&g_sum2[c], s);
    atomicAdd(&g_sq2[c], q);
}

// ---------------- BN params ---------------------------------------------------
template<int STAGE>
__global__ void k_params(const float* __restrict__ g, const float* __restrict__ be) {
    constexpr int C = (STAGE == 3) ? 512 : 256;
    const float* su = (STAGE == 2) ? g_sum2 : (STAGE == 3) ? g_sum3 : g_sum4;
    const float* sq = (STAGE == 2) ? g_sq2  : (STAGE == 3) ? g_sq3  : g_sq4;
    float* sc = (STAGE == 2) ? g_s2 : (STAGE == 3) ? g_s3 : g_s4;
    float* sh = (STAGE == 2) ? g_t2 : (STAGE == 3) ? g_t3 : g_t4;
    int c = blockIdx.x*blockDim.x + threadIdx.x;
    if (c < C) {
        const float inv = 1.0f / (float)MTOT;
        float mean = su[c]*inv;
        float var  = fmaf(-mean, mean, sq[c]*inv);
        float r    = rsqrtf(var + 1e-5f);
        float s    = g[c]*r;
        sc[c] = s;
        sh[c] = fmaf(-mean, s, be[c]);
    }
}

// ---- c1: xm[c][bs] = max_k relu(aff2(y1h)) (no activation store) -------------
__global__ void k_c1() {
    int bs = blockIdx.x;      // 4096
    int c  = threadIdx.x;     // 256
    float sc = g_s2[c], hh = g_t2[c];
    size_t base = (size_t)bs*32*256 + c;
    float mx = 0.f;
    #pragma unroll 8
    for (int pp = 0; pp < 32; ++pp) {
        float v = __half2float(g_y1h[base + (size_t)pp*256]);
        mx = fmaxf(mx, fmaf(v, sc, hh));
    }
    g_xm[c*(BB*NSAMP) + bs] = fmaxf(mx, 0.f);
}

// ---------------- small fp32 GEMM: h3 = w3[:, :256] @ xm ----------------------
__global__ void __launch_bounds__(256, 2) k_gemm0(const float* __restrict__ A) {
    constexpr int Nn = BB*NSAMP;     // 4096
    constexpr int Kd = 256, lda = 512;
    __shared__ unsigned long long As[16][128];
    __shared__ float Bs[16][128];
    int m0 = blockIdx.x * 128;
    int n0 = blockIdx.y * 128;
    int t  = threadIdx.x;
    int ar  = t & 127, akq = (t >> 7) * 8;
    int bkr = t >> 4,  bnc = (t & 15) * 8;
    int ty = t >> 4, tx = t & 15;
    unsigned long long acc[8][4];
    #pragma unroll
    for (int i = 0; i < 8; ++i)
        #pragma unroll
        for (int j = 0; j < 4; ++j) acc[i][j] = 0ull;
    for (int k0 = 0; k0 < Kd; k0 += 16) {
        const float* ga = A + (size_t)(m0 + ar)*lda + k0 + akq;
        float4 a0 = *(const float4*)ga;
        float4 a1 = *(const float4*)(ga + 4);
        const float* gb = g_xm + (size_t)(k0 + bkr)*Nn + n0 + bnc;
        float4 b0 = *(const float4*)gb;
        float4 b1 = *(const float4*)(gb + 4);
        __syncthreads();
        As[akq+0][ar] = dup2(a0.x); As[akq+1][ar] = dup2(a0.y);
        As[akq+2][ar] = dup2(a0.z); As[akq+3][ar] = dup2(a0.w);
        As[akq+4][ar] = dup2(a1.x); As[akq+5][ar] = dup2(a1.y);
        As[akq+6][ar] = dup2(a1.z); As[akq+7][ar] = dup2(a1.w);
        *(float4*)&Bs[bkr][bnc]     = b0;
        *(float4*)&Bs[bkr][bnc + 4] = b1;
        __syncthreads();
        #pragma unroll
        for (int kk = 0; kk < 16; ++kk) {
            unsigned long long af[8], bf[4];
            const unsigned long long* ap = &As[kk][ty*8];
            #pragma unroll
            for (int i = 0; i < 8; ++i) af[i] = ap[i];
            const unsigned long long* bp = (const unsigned long long*)&Bs[kk][tx*8];
            #pragma unroll
            for (int j = 0; j < 4; ++j) bf[j] = bp[j];
            #pragma unroll
            for (int i = 0; i < 8; ++i)
                #pragma unroll
                for (int j = 0; j < 4; ++j)
                    asm("fma.rn.f32x2 %0, %1, %2, %0;"
                        : "+l"(acc[i][j]) : "l"(af[i]), "l"(bf[j]));
        }
    }
    #pragma unroll
    for (int i = 0; i < 8; ++i) {
        int gr = m0 + ty*8 + i;
        float out[8];
        #pragma unroll
        for (int j = 0; j < 4; ++j) {
            out[2*j]   = __uint_as_float((unsigned int)(acc[i][j] & 0xffffffffull));
            out[2*j+1] = __uint_as_float((unsigned int)(acc[i][j] >> 32));
        }
        float4* cp = (float4*)(g_h3 + (size_t)gr*Nn + n0 + tx*8);
        cp[0] = make_float4(out[0], out[1], out[2], out[3]);
        cp[1] = make_float4(out[4], out[5], out[6], out[7]);
    }
}

// ---------------- mma.sync fp16 GEMM, CTA 128x256, inline B transform ---------
// B operand loaded RAW (y1h / y3h); relu(aff) applied in-smem per K-chunk with
// fp32 math identical to the old c1/c3 kernels (bit-identical MMA inputs).
// MODE 1: y3h[n][512] = fp16(w3b @ relu(aff2(y1h))^T + h3), stats3
// MODE 2: y4max[c][bs] = max_k (w4 @ relu(aff3(y3h))^T), stats4
#define STG_BYTES 30720
#define PAR_OFF   92160                  // float2 params after 3 stages
#define MMA_SMEM  96256                  // 92160 + 4096

template<int MODE>
__device__ __forceinline__ void mma_issue(uint32_t sbase, int st, int k0,
                                          int m0c, int n0c, int tid) {
    constexpr int Kd = (MODE == 1) ? 256 : 512;
    const __half* __restrict__ Ah = (MODE == 1) ? g_w3bh : g_w4h;
    const __half* __restrict__ Bh = (MODE == 1) ? g_y1h : g_y3h;   // RAW
    uint32_t base = sbase + st*STG_BYTES;
    #pragma unroll
    for (int i = 0; i < 2; ++i) {
        int u = tid + i*256;
        int r = u >> 2, q = u & 3;
        const __half* src = Ah + (size_t)(m0c + r)*Kd + k0 + q*8;
        CP_ASYNC16(base + r*80 + q*16, src);
    }
    #pragma unroll
    for (int i = 0; i < 4; ++i) {
        int u = tid + i*256;
        int r = u >> 2, q = u & 3;
        const __half* src = Bh + (size_t)(n0c + r)*Kd + k0 + q*8;
        CP_ASYNC16(base + 10240 + r*80 + q*16, src);
    }
}

template<int MODE>
__global__ void __launch_bounds__(256) k_mma() {
    constexpr int Kd = (MODE == 1) ? 256 : 512;
    constexpr int KT = Kd / 32;
    float* __restrict__ Su = (MODE == 1) ? g_sum3 : g_sum4;
    float* __restrict__ Sq = (MODE == 1) ? g_sq3 : g_sq4;
    const float* __restrict__ S = (MODE == 1) ? g_s2 : g_s3;
    const float* __restrict__ T = (MODE == 1) ? g_t2 : g_t3;

    extern __shared__ char smem[];
    uint32_t sb = smem_to_u32(smem);
    int tid = threadIdx.x, lane = tid & 31, wid = tid >> 5;
    int wm = wid >> 2, wn = wid & 3;
    int m0c = blockIdx.x * 128, n0c = blockIdx.y * 256;

    // per-channel (scale, shift) into smem
    float2* par = (float2*)(smem + PAR_OFF);
    for (int i = tid; i < Kd; i += 256) par[i] = make_float2(S[i], T[i]);

    float acc[4][8][4];
    #pragma unroll
    for (int a = 0; a < 4; ++a)
        #pragma unroll
        for (int b = 0; b < 8; ++b)
            #pragma unroll
            for (int c = 0; c < 4; ++c) acc[a][b][c] = 0.f;

    int sel = lane >> 3;
    uint32_t aRow = (uint32_t)((sel & 1)*8 + (lane & 7));
    uint32_t aCol = (uint32_t)((sel >> 1) * 16);
    uint32_t bRowB = (uint32_t)(wn*64 + (lane & 7));
    uint32_t bCol = (uint32_t)(((lane >> 3) & 1) * 16);

    mma_issue<MODE>(sb, 0, 0,  m0c, n0c, tid); CP_COMMIT();
    mma_issue<MODE>(sb, 1, 32, m0c, n0c, tid); CP_COMMIT();

    for (int kt = 0; kt < KT; ++kt) {
        if (kt == KT-1) { CP_WAIT0(); } else { CP_WAIT1(); }
        __syncthreads();
        if (kt + 2 < KT) {
            mma_issue<MODE>(sb, (kt+2)%3, (kt+2)*32, m0c, n0c, tid);
            CP_COMMIT();
        }
        char* stage = smem + (kt%3)*STG_BYTES;
        int k0 = kt*32;
        // ---- in-smem B transform: relu(v*s + t), fp32 math, repack fp16 ----
        #pragma unroll
        for (int i = 0; i < 4; ++i) {
            int u = tid + i*256;
            int r = u >> 2, q = u & 3;
            char* addr = stage + 10240 + r*80 + q*16;
            uint4 v = *(uint4*)addr;
            __half2* hh = (__half2*)&v;
            int kb = k0 + q*8;
            #pragma unroll
            for (int e = 0; e < 4; ++e) {
                float2 pa = par[kb + 2*e];
                float2 pb2 = par[kb + 2*e + 1];
                float lo = __low2float(hh[e]), hi = __high2float(hh[e]);
                lo = fmaxf(fmaf(lo, pa.x, pa.y), 0.f);
                hi = fmaxf(fmaf(hi, pb2.x, pb2.y), 0.f);
                hh[e] = __floats2half2_rn(lo, hi);
            }
            *(uint4*)addr = v;
        }
        __syncthreads();

        uint32_t sA = sb + (kt%3)*STG_BYTES;
        uint32_t sBB = sA + 10240;
        #pragma unroll
        for (int ks = 0; ks < 2; ++ks) {
            uint32_t kOff = (uint32_t)(ks*32);
            uint32_t ah[4][4], bf[8][2];
            #pragma unroll
            for (int mt = 0; mt < 4; ++mt)
                ldsm_x4(ah[mt][0], ah[mt][1], ah[mt][2], ah[mt][3],
                        sA + (uint32_t)(wm*64 + mt*16 + aRow)*80 + kOff + aCol);
            #pragma unroll
            for (int nt = 0; nt < 8; ++nt)
                ldsm_x2(bf[nt][0], bf[nt][1],
                        sBB + (bRowB + (uint32_t)(nt*8))*80 + kOff + bCol);
            #pragma unroll
            for (int mt = 0; mt < 4; ++mt)
                #pragma unroll
                for (int nt = 0; nt < 8; ++nt)
                    mma16816(acc[mt][nt], ah[mt], bf[nt]);
        }
    }

    // ---------------- epilogue ------------------------------------------------
    __syncthreads();
    __half* st = (__half*)smem;              // 256 x 128 halves (64KB), MODE 1
    float* redS = (float*)(smem + 65536);    // [128][16]
    float* redQ = (float*)(smem + 73728);
    int qrow = lane >> 2, qcol = lane & 3;

    #pragma unroll
    for (int mt = 0; mt < 4; ++mt) {
        #pragma unroll
        for (int hf = 0; hf < 2; ++hf) {
            int mloc = wm*64 + mt*16 + hf*8 + qrow;
            int mg = m0c + mloc;
            float h3a = 0.f, h3b = 0.f;
            if (MODE == 1) {
                int gidx = (n0c >> 5) + wn*2;
                h3a = g_h3[(size_t)mg*(BB*NSAMP) + gidx];
                h3b = g_h3[(size_t)mg*(BB*NSAMP) + gidx + 1];
            }
            float s = 0.f, q = 0.f;
            float mx0 = -1e30f, mx1 = -1e30f;
            #pragma unroll
            for (int nt = 0; nt < 8; ++nt) {
                float h3v = (nt < 4) ? h3a : h3b;
                #pragma unroll
                for (int j = 0; j < 2; ++j) {
                    float v = acc[mt][nt][hf*2 + j] + h3v;
                    s += v; q = fmaf(v, v, q);
                    if (MODE == 1) {
                        int nl = wn*64 + nt*8 + qcol*2 + j;
                        st[nl*128 + mloc] = __float2half(v);
                    } else {
                        if (nt < 4) mx0 = fmaxf(mx0, v); else mx1 = fmaxf(mx1, v);
                    }
                }
            }
            if (MODE == 2) {
                mx0 = fmaxf(mx0, __shfl_xor_sync(0xffffffffu, mx0, 1));
                mx0 = fmaxf(mx0, __shfl_xor_sync(0xffffffffu, mx0, 2));
                mx1 = fmaxf(mx1, __shfl_xor_sync(0xffffffffu, mx1, 1));
                mx1 = fmaxf(mx1, __shfl_xor_sync(0xffffffffu, mx1, 2));
                if (qcol == 0) {
                    int bsg = (n0c >> 5) + wn*2;
                    g_y4m[mg*(BB*NSAMP) + bsg]     = mx0;
                    g_y4m[mg*(BB*NSAMP) + bsg + 1] = mx1;
                }
            }
            redS[mloc*16 + wn*4 + qcol] = s;
            redQ[mloc*16 + wn*4 + qcol] = q;
        }
    }
    __syncthreads();
    if (MODE == 1) {
        #pragma unroll
        for (int i = 0; i < 16; ++i) {
            int u = tid + i*256;
            int row = u >> 4, seg = u & 15;
            uint4 v = *(uint4*)(st + row*128 + seg*8);
            *(uint4*)(g_y3h + (size_t)(n0c + row)*512 + m0c + seg*8) = v;
        }
    }
    if (tid < 128) {
        float s = 0.f;
        #pragma unroll
        for (int i = 0; i < 16; ++i) s += redS[tid*16 + i];
        atomicAdd(&Su[m0c + tid], s);
    } else {
        int m = tid - 128;
        float q = 0.f;
        #pragma unroll
        for (int i = 0; i < 16; ++i) q += redQ[m*16 + i];
        atomicAdd(&Sq[m0c + m], q);
    }
}

// ---------------- fin2: out_feat = relu(aff4(y4max)) --------------------------
__global__ void k_fin2(float* __restrict__ out) {
    int c = blockIdx.x;        // 256
    int b = blockIdx.y;        // 4
    int s = threadIdx.x;       // 1024
    int bs = b*1024 + s;
    float v = g_y4m[c*(BB*NSAMP) + bs];
    float o = fmaxf(fmaf(v, g_s4[c], g_t4[c]), 0.f);
    out[(((b << 8) + c) << 10) + s] = o;
}

// ---------------- launcher ----------------------------------------------------
extern "C" void kernel_launch(void* const* d_in, const int* in_sizes, int n_in,
                              void* d_out, int out_size) {
    const float* p   = (const float*)d_in[0];
    const float* f   = (const float*)d_in[1];
    const float* w1  = (const float*)d_in[2];
    const float* w2  = (const float*)d_in[3];
    const float* b2  = (const float*)d_in[4];
    const float* g2  = (const float*)d_in[5];
    const float* be2 = (const float*)d_in[6];
    const float* w3  = (const float*)d_in[7];
    const float* g3  = (const float*)d_in[8];
    const float* be3 = (const float*)d_in[9];
    const float* w4  = (const float*)d_in[10];
    const float* g4  = (const float*)d_in[11];
    const float* be4 = (const float*)d_in[12];
    float* out = (float*)d_out;

    cudaFuncSetAttribute(k_mma<1>, cudaFuncAttributeMaxDynamicSharedMemorySize, MMA_SMEM);
    cudaFuncSetAttribute(k_mma<2>, cudaFuncAttributeMaxDynamicSharedMemorySize, MMA_SMEM);

    k_zero<<<1, 512>>>();
    k_w21<<<1, 256>>>(w1, w2);
    k_wsplit<<<512, 256>>>(w3, w4);
    k_fps<<<BB, 512>>>(p, out);                        // cntrd -> d_out[0..12288)
    k_knn<<<BB*NSAMP, 128>>>(p, out);
    k_gconv1<<<MTOT/64, 256>>>(p, f, b2);              // y1h raw fp16 + stats2
    k_params<2><<<2, 256>>>(g2, be2);
    k_c1<<<BB*NSAMP, 256>>>();                         // xm only
    k_gemm0<<<dim3(4, 32), 256>>>(w3);                 // h3 = w3a @ xm
    k_mma<1><<<dim3(4, 512), 256, MMA_SMEM>>>();       // y3h raw fp16 + stats3
    k_params<3><<<2, 256>>>(g3, be3);
    k_mma<2><<<dim3(2, 512), 256, MMA_SMEM>>>();       // y4max + stats4
    k_params<4><<<2, 256>>>(g4, be4);
    k_fin2<<<dim3(256, 4), 1024>>>(out + BB*NSAMP*3);
}

// round 16
// speedup vs baseline: 1.2670x; 1.2670x over previous
#include <cuda_runtime.h>
#include <cuda_fp16.h>
#include <cstdint>

#define BB 4
#define NN 4096
#define NSAMP 1024
#define KNB 32
#define MTOT (BB*NSAMP*KNB)   // 131072 positions

// ---------------- scratch (device globals; no allocations allowed) ------------
__device__ float g_w21[256*6];
__device__ unsigned g_prog[4];                 // fps progress per batch
__device__ __half g_y1h[(size_t)MTOT*256];     // conv1 out RAW fp16, [m][c]
__device__ __half g_y1a[(size_t)MTOT*256];     // relu(aff2(y1)) fp16, [m][c]
__device__ float g_xm[256*BB*NSAMP];           // [c][bs]
__device__ float g_h3[512*BB*NSAMP];           // [row][bs]
__device__ __half g_y3h[(size_t)MTOT*512];     // conv3 out RAW fp16, [n][512]
__device__ __half g_y3a[(size_t)MTOT*512];     // relu(aff3(y3)) fp16
__device__ float g_y4m[256*BB*NSAMP];          // max_k of RAW y4, [c][bs]
__device__ __half g_w3bh[512*256];
__device__ __half g_w4h[256*512];
__device__ float g_sum2[256], g_sq2[256];
__device__ float g_sum3[512], g_sq3[512];
__device__ float g_sum4[256], g_sq4[256];
__device__ float g_s2[256], g_t2[256];
__device__ float g_s3[512], g_t3[512];
__device__ float g_s4[256], g_t4[256];

// ---------------- helpers -----------------------------------------------------
__device__ __forceinline__ uint32_t smem_to_u32(const void* p) {
    uint32_t a;
    asm("{ .reg .u64 t; cvta.to.shared.u64 t, %1; cvt.u32.u64 %0, t; }" : "=r"(a) : "l"(p));
    return a;
}
__device__ __forceinline__ unsigned long long dup2(float a) {
    unsigned int u = __float_as_uint(a);
    return ((unsigned long long)u << 32) | (unsigned long long)u;
}
__device__ __forceinline__ unsigned long long pk64(float a, float b) {
    unsigned long long r;
    asm("mov.b64 %0, {%1,%2};" : "=l"(r) : "f"(a), "f"(b));
    return r;
}
__device__ __forceinline__ void up64(float& a, float& b, unsigned long long v) {
    asm("mov.b64 {%0,%1}, %2;" : "=f"(a), "=f"(b) : "l"(v));
}
__device__ __forceinline__ unsigned long long fma2(unsigned long long a,
                                                   unsigned long long b,
                                                   unsigned long long c) {
    unsigned long long r;
    asm("fma.rn.f32x2 %0, %1, %2, %3;" : "=l"(r) : "l"(a), "l"(b), "l"(c));
    return r;
}
__device__ __forceinline__ unsigned int fmono(float f) {
    unsigned int u = __float_as_uint(f);
    return (u & 0x80000000u) ? ~u : (u | 0x80000000u);
}
__device__ __forceinline__ uint32_t pk2h(__half a, __half b) {
    return ((uint32_t)__half_as_ushort(b) << 16) | (uint32_t)__half_as_ushort(a);
}
__device__ __forceinline__ void st_rel(unsigned* p, unsigned v) {
    asm volatile("st.release.gpu.global.u32 [%0], %1;" :: "l"(p), "r"(v) : "memory");
}
__device__ __forceinline__ unsigned ld_acq(unsigned* p) {
    unsigned v;
    asm volatile("ld.acquire.gpu.global.u32 %0, [%1];" : "=r"(v) : "l"(p) : "memory");
    return v;
}
#define UBAR(id) asm volatile("bar.sync %0, 128;" :: "r"(id) : "memory")

#define CP_ASYNC16(dst, src) \
    asm volatile("cp.async.cg.shared.global [%0], [%1], 16;" :: "r"(dst), "l"(src) : "memory")
#define CP_COMMIT() asm volatile("cp.async.commit_group;" ::: "memory")
#define CP_WAIT0() asm volatile("cp.async.wait_group 0;" ::: "memory")
#define CP_WAIT1() asm volatile("cp.async.wait_group 1;" ::: "memory")

__device__ __forceinline__ void ldsm_x4(uint32_t& r0, uint32_t& r1, uint32_t& r2, uint32_t& r3, uint32_t addr) {
    asm volatile("ldmatrix.sync.aligned.m8n8.x4.shared.b16 {%0,%1,%2,%3}, [%4];"
        : "=r"(r0), "=r"(r1), "=r"(r2), "=r"(r3) : "r"(addr));
}
__device__ __forceinline__ void ldsm_x2(uint32_t& r0, uint32_t& r1, uint32_t addr) {
    asm volatile("ldmatrix.sync.aligned.m8n8.x2.shared.b16 {%0,%1}, [%2];"
        : "=r"(r0), "=r"(r1) : "r"(addr));
}
__device__ __forceinline__ void mma16816(float* d, const uint32_t* a, const uint32_t* b) {
    asm volatile("mma.sync.aligned.m16n8k16.row.col.f32.f16.f16.f32 "
        "{%0,%1,%2,%3}, {%4,%5,%6,%7}, {%8,%9}, {%0,%1,%2,%3};"
        : "+f"(d[0]), "+f"(d[1]), "+f"(d[2]), "+f"(d[3])
        : "r"(a[0]), "r"(a[1]), "r"(a[2]), "r"(a[3]), "r"(b[0]), "r"(b[1]));
}

// ---------------- zero stats + progress ---------------------------------------
__global__ void k_zero() {
    int t = threadIdx.x;  // 512
    if (t < 256) { g_sum2[t]=0.f; g_sq2[t]=0.f; g_sum4[t]=0.f; g_sq4[t]=0.f; }
    g_sum3[t]=0.f; g_sq3[t]=0.f;
    if (t < 4) g_prog[t] = 0u;
}

// ---------------- w21 = w2 @ w1 -----------------------------------------------
__global__ void k_w21(const float* __restrict__ w1, const float* __restrict__ w2) {
    int o = threadIdx.x;
    float acc[6] = {0.f,0.f,0.f,0.f,0.f,0.f};
    for (int c = 0; c < 256; ++c) {
        float w = w2[o*256 + c];
        #pragma unroll
        for (int i = 0; i < 6; ++i) acc[i] = fmaf(w, w1[c*6+i], acc[i]);
    }
    #pragma unroll
    for (int i = 0; i < 6; ++i) g_w21[o*6+i] = acc[i];
}

// ---------------- weight fp16 -------------------------------------------------
__global__ void k_wsplit(const float* __restrict__ w3, const float* __restrict__ w4) {
    int i = blockIdx.x*256 + threadIdx.x;   // 0..131071
    int r = i >> 8, c = i & 255;
    g_w3bh[i] = __float2half(w3[r*512 + 256 + c]);
    g_w4h[i]  = __float2half(w4[i]);
}

// ======== FUSED: fps producers (blocks 0-3) + knn/gconv1 consumers ============
// 132 blocks x 512 thr, single wave. Producer publishes progress every 32
// centroids (fence amortized); consumer block = 4 independent 128-thread units.
__global__ void __launch_bounds__(512, 1) k_fused(const float* __restrict__ p,
                                                  const float* __restrict__ f,
                                                  const float* __restrict__ b2,
                                                  float* __restrict__ outC) {
    int t = threadIdx.x;

    if (blockIdx.x < 4) {
        // ------------------------- FPS producer -------------------------------
        __shared__ unsigned s_v[2][16];
        __shared__ unsigned s_i[2][16];
        int b = blockIdx.x;
        const float* pb = p + b*NN*3;
        int lane = t & 31, w = t >> 5;

        float dm[8];
        unsigned long long pX[4], pY[4], pZ[4];
        #pragma unroll
        for (int j = 0; j < 4; ++j) {
            int i0 = t + (2*j)*512, i1 = t + (2*j+1)*512;
            pX[j] = pk64(pb[i0*3],   pb[i1*3]);
            pY[j] = pk64(pb[i0*3+1], pb[i1*3+1]);
            pZ[j] = pk64(pb[i0*3+2], pb[i1*3+2]);
            dm[2*j] = 1e10f; dm[2*j+1] = 1e10f;
        }
        const unsigned long long NEG1 = dup2(-1.0f);

        float cx = pb[0], cy = pb[1], cz = pb[2];
        if (t == 0) {
            float* o = outC + b*NSAMP*3;
            o[0] = cx; o[1] = cy; o[2] = cz;
            st_rel(&g_prog[b], 1u);
        }

        for (int it = 0; it < NSAMP; ++it) {
            int buf = it & 1;
            unsigned long long c2x = dup2(cx), c2y = dup2(cy), c2z = dup2(cz);
            #pragma unroll
            for (int j = 0; j < 4; ++j) {
                unsigned long long tx = fma2(c2x, NEG1, pX[j]);
                unsigned long long ty = fma2(c2y, NEG1, pY[j]);
                unsigned long long tz = fma2(c2z, NEG1, pZ[j]);
                unsigned long long d2 = fma2(tx, tx, 0ull);
                d2 = fma2(ty, ty, d2);
                d2 = fma2(tz, tz, d2);
                float da, db; up64(da, db, d2);
                dm[2*j]   = fminf(dm[2*j],   da);
                dm[2*j+1] = fminf(dm[2*j+1], db);
            }

            float best = dm[0];
            #pragma unroll
            for (int j = 1; j < 8; ++j) best = fmaxf(best, dm[j]);
            int bi = t + 7*512;
            #pragma unroll
            for (int j = 6; j >= 0; --j) if (dm[j] == best) bi = t + j*512;

            unsigned mv   = fmono(best);
            unsigned wmax = __reduce_max_sync(0xffffffffu, mv);
            unsigned cand = (mv == wmax) ? (unsigned)bi : 0xffffffffu;
            unsigned widx = __reduce_min_sync(0xffffffffu, cand);
            if (lane == 0) { s_v[buf][w] = wmax; s_i[buf][w] = widx; }
            __syncthreads();

            unsigned mv2 = (lane < 16) ? s_v[buf][lane] : 0u;
            unsigned id2 = (lane < 16) ? s_i[buf][lane] : 0xffffffffu;
            unsigned m2  = __reduce_max_sync(0xffffffffu, mv2);
            unsigned c2v = (mv2 == m2) ? id2 : 0xffffffffu;
            unsigned far = __reduce_min_sync(0xffffffffu, c2v);

            cx = pb[far*3]; cy = pb[far*3+1]; cz = pb[far*3+2];
            if (t == 0 && it + 1 < NSAMP) {
                float* o = outC + (b*NSAMP + it + 1)*3;
                o[0] = cx; o[1] = cy; o[2] = cz;
                if (((it + 2) & 31) == 0)                 // 32 fences total
                    st_rel(&g_prog[b], (unsigned)(it + 2));
            }
        }
    } else {
        // ------------------- consumer: 4 x 128-thread knn units ----------------
        __shared__ float sw[1536];
        __shared__ float sbb[256];
        __shared__ float sv4[4][32][6];
        __shared__ int   sidx4[4][32];
        __shared__ unsigned sh4[4][2][4], sl4[4][2][4];

        for (int i = t; i < 1536; i += 512) sw[i] = g_w21[i];
        if (t < 256) sbb[t] = b2[t];
        __syncthreads();

        int su = t >> 7;            // unit 0..3 == batch
        int tl = t & 127;           // local thread within unit
        int wl = tl >> 5, lane = t & 31;
        int cb = blockIdx.x - 4;    // 0..127
        int b = su;
        const float* pb = p + b*NN*3;
        const float* fb = f + b*3*NN;
        int bar = su + 1;

        int c0 = tl, c1 = tl + 128;
        float wA0=sw[c0*6],wA1=sw[c0*6+1],wA2=sw[c0*6+2];
        float wA3=sw[c0*6+3],wA4=sw[c0*6+4],wA5=sw[c0*6+5];
        float wB0=sw[c1*6],wB1=sw[c1*6+1],wB2=sw[c1*6+2];
        float wB3=sw[c1*6+3],wB4=sw[c1*6+4],wB5=sw[c1*6+5];
        float bias0 = sbb[c0], bias1 = sbb[c1];
        float s0=0.f,q0=0.f,s1=0.f,q1=0.f;

        for (int g = 0; g < 8; ++g) {
            int sI = g*128 + cb;
            int cid = b*1024 + sI;

            if (tl == 0) {
                while ((int)ld_acq(&g_prog[b]) <= sI) __nanosleep(256);
            }
            UBAR(bar);

            float cx = __ldcg(outC + cid*3);
            float cy = __ldcg(outC + cid*3 + 1);
            float cz = __ldcg(outC + cid*3 + 2);
            float cn = cx*cx + cy*cy + cz*cz;

            unsigned long long key[32];
            #pragma unroll
            for (int j = 0; j < 32; ++j) {
                int i = j*128 + tl;
                float x = pb[i*3], y = pb[i*3+1], z = pb[i*3+2];
                float pn = x*x + y*y + z*z;
                float dot = fmaf(cx, x, fmaf(cy, y, cz*z));
                float d2  = fmaf(-2.0f, dot, cn + pn);
                key[j] = ((unsigned long long)fmono(d2) << 32) | (unsigned int)i;
            }

            unsigned long long prev = 0ull;
            for (int r = 0; r < KNB; ++r) {
                int rb = r & 1;
                unsigned long long b0 = ~0ull, b1 = ~0ull, b2k = ~0ull, b3 = ~0ull;
                #pragma unroll
                for (int j = 0; j < 8; ++j) {
                    unsigned long long k0 = key[j];
                    if (k0 > prev && k0 < b0) b0 = k0;
                    unsigned long long k1 = key[8 + j];
                    if (k1 > prev && k1 < b1) b1 = k1;
                    unsigned long long k2 = key[16 + j];
                    if (k2 > prev && k2 < b2k) b2k = k2;
                    unsigned long long k3 = key[24 + j];
                    if (k3 > prev && k3 < b3) b3 = k3;
                }
                if (b1 < b0) b0 = b1;
                if (b3 < b2k) b2k = b3;
                unsigned long long best = (b2k < b0) ? b2k : b0;

                unsigned bh = (unsigned)(best >> 32), bl = (unsigned)best;
                unsigned mh = __reduce_min_sync(0xffffffffu, bh);
                unsigned cl = (bh == mh) ? bl : 0xffffffffu;
                unsigned ml = __reduce_min_sync(0xffffffffu, cl);
                if (lane == 0) { sh4[su][rb][wl] = mh; sl4[su][rb][wl] = ml; }
                UBAR(bar);

                unsigned fh = sh4[su][rb][0], fl = sl4[su][rb][0];
                #pragma unroll
                for (int i = 1; i < 4; ++i) {
                    unsigned hh = sh4[su][rb][i], ll = sl4[su][rb][i];
                    if (hh < fh || (hh == fh && ll < fl)) { fh = hh; fl = ll; }
                }
                prev = ((unsigned long long)fh << 32) | fl;
                if (tl == 0) sidx4[su][r] = (int)fl;
            }
            UBAR(bar);                      // sidx writes visible

            if (tl < 32) {
                int idx = sidx4[su][tl];
                const float* pp = pb + idx*3;
                sv4[su][tl][0] = pp[0]; sv4[su][tl][1] = pp[1]; sv4[su][tl][2] = pp[2];
                sv4[su][tl][3] = fb[idx]; sv4[su][tl][4] = fb[NN + idx];
                sv4[su][tl][5] = fb[2*NN + idx];
            }
            UBAR(bar);

            size_t mbase = (size_t)cid*32;
            #pragma unroll 4
            for (int pp = 0; pp < 32; ++pp) {
                float v0 = sv4[su][pp][0], v1 = sv4[su][pp][1], v2 = sv4[su][pp][2];
                float v3 = sv4[su][pp][3], v4 = sv4[su][pp][4], v5 = sv4[su][pp][5];
                float a0 = bias0;
                a0 = fmaf(wA0, v0, a0); a0 = fmaf(wA1, v1, a0); a0 = fmaf(wA2, v2, a0);
                a0 = fmaf(wA3, v3, a0); a0 = fmaf(wA4, v4, a0); a0 = fmaf(wA5, v5, a0);
                float a1 = bias1;
                a1 = fmaf(wB0, v0, a1); a1 = fmaf(wB1, v1, a1); a1 = fmaf(wB2, v2, a1);
                a1 = fmaf(wB3, v3, a1); a1 = fmaf(wB4, v4, a1); a1 = fmaf(wB5, v5, a1);
                g_y1h[(mbase + pp)*256 + c0] = __float2half(a0);
                g_y1h[(mbase + pp)*256 + c1] = __float2half(a1);
                s0 += a0; q0 = fmaf(a0, a0, q0);
                s1 += a1; q1 = fmaf(a1, a1, q1);
            }
            UBAR(bar);                      // protect sv4/sidx4 for next centroid
        }
        atomicAdd(&g_sum2[c0], s0); atomicAdd(&g_sq2[c0], q0);
        atomicAdd(&g_sum2[c1], s1); atomicAdd(&g_sq2[c1], q1);
    }
}

// ---------------- BN params ---------------------------------------------------
template<int STAGE>
__global__ void k_params(const float* __restrict__ g, const float* __restrict__ be) {
    constexpr int C = (STAGE == 3) ? 512 : 256;
    const float* su = (STAGE == 2) ? g_sum2 : (STAGE == 3) ? g_sum3 : g_sum4;
    const float* sq = (STAGE == 2) ? g_sq2  : (STAGE == 3) ? g_sq3  : g_sq4;
    float* sc = (STAGE == 2) ? g_s2 : (STAGE == 3) ? g_s3 : g_s4;
    float* sh = (STAGE == 2) ? g_t2 : (STAGE == 3) ? g_t3 : g_t4;
    int c = blockIdx.x*blockDim.x + threadIdx.x;
    if (c < C) {
        const float inv = 1.0f / (float)MTOT;
        float mean = su[c]*inv;
        float var  = fmaf(-mean, mean, sq[c]*inv);
        float r    = rsqrtf(var + 1e-5f);
        float s    = g[c]*r;
        sc[c] = s;
        sh[c] = fmaf(-mean, s, be[c]);
    }
}

// ---- c1: relu(aff2(y1h)) -> fp16 [m][256] + xm [c][bs] -----------------------
__global__ void k_c1() {
    int bs = blockIdx.x;      // 4096
    int c  = threadIdx.x;     // 256
    float sc = g_s2[c], hh = g_t2[c];
    size_t base = (size_t)bs*32*256 + c;
    float mx = 0.f;
    #pragma unroll 8
    for (int pp = 0; pp < 32; ++pp) {
        float v = __half2float(g_y1h[base + (size_t)pp*256]);
        float a = fmaxf(fmaf(v, sc, hh), 0.f);
        mx = fmaxf(mx, a);
        g_y1a[base + (size_t)pp*256] = __float2half(a);
    }
    g_xm[c*(BB*NSAMP) + bs] = mx;
}

// ---- c3: relu(aff3(y3h)) -> fp16 [n][512] ------------------------------------
__global__ void k_c3() {
    size_t i = (size_t)blockIdx.x*256 + threadIdx.x;   // uint2 index (16.7M)
    uint2 r = ((const uint2*)g_y3h)[i];
    int k = ((int)(i & 127)) * 4;
    __half2 v01 = *(__half2*)&r.x;
    __half2 v23 = *(__half2*)&r.y;
    float a0 = fmaxf(fmaf(__low2float(v01),  g_s3[k],   g_t3[k]),   0.f);
    float a1 = fmaxf(fmaf(__high2float(v01), g_s3[k+1], g_t3[k+1]), 0.f);
    float a2 = fmaxf(fmaf(__low2float(v23),  g_s3[k+2], g_t3[k+2]), 0.f);
    float a3 = fmaxf(fmaf(__high2float(v23), g_s3[k+3], g_t3[k+3]), 0.f);
    ((uint2*)g_y3a)[i] = make_uint2(pk2h(__float2half(a0), __float2half(a1)),
                                   pk2h(__float2half(a2), __float2half(a3)));
}

// ---------------- small fp32 GEMM: h3 = w3[:, :256] @ xm ----------------------
__global__ void __launch_bounds__(256, 2) k_gemm0(const float* __restrict__ A) {
    constexpr int Nn = BB*NSAMP;     // 4096
    constexpr int Kd = 256, lda = 512;
    __shared__ unsigned long long As[16][128];
    __shared__ float Bs[16][128];
    int m0 = blockIdx.x * 128;
    int n0 = blockIdx.y * 128;
    int t  = threadIdx.x;
    int ar  = t & 127, akq = (t >> 7) * 8;
    int bkr = t >> 4,  bnc = (t & 15) * 8;
    int ty = t >> 4, tx = t & 15;
    unsigned long long acc[8][4];
    #pragma unroll
    for (int i = 0; i < 8; ++i)
        #pragma unroll
        for (int j = 0; j < 4; ++j) acc[i][j] = 0ull;
    for (int k0 = 0; k0 < Kd; k0 += 16) {
        const float* ga = A + (size_t)(m0 + ar)*lda + k0 + akq;
        float4 a0 = *(const float4*)ga;
        float4 a1 = *(const float4*)(ga + 4);
        const float* gb = g_xm + (size_t)(k0 + bkr)*Nn + n0 + bnc;
        float4 b0 = *(const float4*)gb;
        float4 b1 = *(const float4*)(gb + 4);
        __syncthreads();
        As[akq+0][ar] = dup2(a0.x); As[akq+1][ar] = dup2(a0.y);
        As[akq+2][ar] = dup2(a0.z); As[akq+3][ar] = dup2(a0.w);
        As[akq+4][ar] = dup2(a1.x); As[akq+5][ar] = dup2(a1.y);
        As[akq+6][ar] = dup2(a1.z); As[akq+7][ar] = dup2(a1.w);
        *(float4*)&Bs[bkr][bnc]     = b0;
        *(float4*)&Bs[bkr][bnc + 4] = b1;
        __syncthreads();
        #pragma unroll
        for (int kk = 0; kk < 16; ++kk) {
            unsigned long long af[8], bf[4];
            const unsigned long long* ap = &As[kk][ty*8];
            #pragma unroll
            for (int i = 0; i < 8; ++i) af[i] = ap[i];
            const unsigned long long* bp = (const unsigned long long*)&Bs[kk][tx*8];
            #pragma unroll
            for (int j = 0; j < 4; ++j) bf[j] = bp[j];
            #pragma unroll
            for (int i = 0; i < 8; ++i)
                #pragma unroll
                for (int j = 0; j < 4; ++j)
                    asm("fma.rn.f32x2 %0, %1, %2, %0;"
                        : "+l"(acc[i][j]) : "l"(af[i]), "l"(bf[j]));
        }
    }
    #pragma unroll
    for (int i = 0; i < 8; ++i) {
        int gr = m0 + ty*8 + i;
        float out[8];
        #pragma unroll
        for (int j = 0; j < 4; ++j) {
            out[2*j]   = __uint_as_float((unsigned int)(acc[i][j] & 0xffffffffull));
            out[2*j+1] = __uint_as_float((unsigned int)(acc[i][j] >> 32));
        }
        float4* cp = (float4*)(g_h3 + (size_t)gr*Nn + n0 + tx*8);
        cp[0] = make_float4(out[0], out[1], out[2], out[3]);
        cp[1] = make_float4(out[4], out[5], out[6], out[7]);
    }
}

// ---------------- mma.sync fp16 GEMM (single pass), CTA 128x256 ---------------
// MODE 1: y3h[n][512] = fp16(w3b @ y1a^T + h3), stats3   (smem-transposed store)
// MODE 2: y4max[c][bs] = max_k (w4 @ y3a^T), stats4      (no bulk store)
#define STG_BYTES 30720
#define MMA_SMEM  92160

template<int MODE>
__device__ __forceinline__ void mma_issue(uint32_t sbase, int st, int k0,
                                          int m0c, int n0c, int tid) {
    constexpr int Kd = (MODE == 1) ? 256 : 512;
    const __half* __restrict__ Ah = (MODE == 1) ? g_w3bh : g_w4h;
    const __half* __restrict__ Bh = (MODE == 1) ? g_y1a : g_y3a;
    uint32_t base = sbase + st*STG_BYTES;
    #pragma unroll
    for (int i = 0; i < 2; ++i) {
        int u = tid + i*256;
        int r = u >> 2, q = u & 3;
        const __half* src = Ah + (size_t)(m0c + r)*Kd + k0 + q*8;
        CP_ASYNC16(base + r*80 + q*16, src);
    }
    #pragma unroll
    for (int i = 0; i < 4; ++i) {
        int u = tid + i*256;
        int r = u >> 2, q = u & 3;
        const __half* src = Bh + (size_t)(n0c + r)*Kd + k0 + q*8;
        CP_ASYNC16(base + 10240 + r*80 + q*16, src);
    }
}

template<int MODE>
__global__ void __launch_bounds__(256) k_mma() {
    constexpr int Kd = (MODE == 1) ? 256 : 512;
    constexpr int KT = Kd / 32;
    float* __restrict__ Su = (MODE == 1) ? g_sum3 : g_sum4;
    float* __restrict__ Sq = (MODE == 1) ? g_sq3 : g_sq4;

    extern __shared__ char smem[];
    uint32_t sb = smem_to_u32(smem);
    int tid = threadIdx.x, lane = tid & 31, wid = tid >> 5;
    int wm = wid >> 2, wn = wid & 3;
    int m0c = blockIdx.x * 128, n0c = blockIdx.y * 256;

    float acc[4][8][4];
    #pragma unroll
    for (int a = 0; a < 4; ++a)
        #pragma unroll
        for (int b = 0; b < 8; ++b)
            #pragma unroll
            for (int c = 0; c < 4; ++c) acc[a][b][c] = 0.f;

    int sel = lane >> 3;
    uint32_t aRow = (uint32_t)((sel & 1)*8 + (lane & 7));
    uint32_t aCol = (uint32_t)((sel >> 1) * 16);
    uint32_t bRowB = (uint32_t)(wn*64 + (lane & 7));
    uint32_t bCol = (uint32_t)(((lane >> 3) & 1) * 16);

    mma_issue<MODE>(sb, 0, 0,  m0c, n0c, tid); CP_COMMIT();
    mma_issue<MODE>(sb, 1, 32, m0c, n0c, tid); CP_COMMIT();

    for (int kt = 0; kt < KT; ++kt) {
        if (kt == KT-1) { CP_WAIT0(); } else { CP_WAIT1(); }
        __syncthreads();
        if (kt + 2 < KT) {
            mma_issue<MODE>(sb, (kt+2)%3, (kt+2)*32, m0c, n0c, tid);
            CP_COMMIT();
        }
        uint32_t sA = sb + (kt%3)*STG_BYTES;
        uint32_t sBB = sA + 10240;
        #pragma unroll
        for (int ks = 0; ks < 2; ++ks) {
            uint32_t kOff = (uint32_t)(ks*32);
            uint32_t ah[4][4], bf[8][2];
            #pragma unroll
            for (int mt = 0; mt < 4; ++mt)
                ldsm_x4(ah[mt][0], ah[mt][1], ah[mt][2], ah[mt][3],
                        sA + (uint32_t)(wm*64 + mt*16 + aRow)*80 + kOff + aCol);
            #pragma unroll
            for (int nt = 0; nt < 8; ++nt)
                ldsm_x2(bf[nt][0], bf[nt][1],
                        sBB + (bRowB + (uint32_t)(nt*8))*80 + kOff + bCol);
            #pragma unroll
            for (int mt = 0; mt < 4; ++mt)
                #pragma unroll
                for (int nt = 0; nt < 8; ++nt)
                    mma16816(acc[mt][nt], ah[mt], bf[nt]);
        }
    }

    // ---------------- epilogue ------------------------------------------------
    __syncthreads();
    __half* st = (__half*)smem;              // 256 x 128 halves (64KB), MODE 1
    float* redS = (float*)(smem + 65536);    // [128][16]
    float* redQ = (float*)(smem + 73728);
    int qrow = lane >> 2, qcol = lane & 3;

    #pragma unroll
    for (int mt = 0; mt < 4; ++mt) {
        #pragma unroll
        for (int hf = 0; hf < 2; ++hf) {
            int mloc = wm*64 + mt*16 + hf*8 + qrow;
            int mg = m0c + mloc;
            float h3a = 0.f, h3b = 0.f;
            if (MODE == 1) {
                int gidx = (n0c >> 5) + wn*2;
                h3a = g_h3[(size_t)mg*(BB*NSAMP) + gidx];
                h3b = g_h3[(size_t)mg*(BB*NSAMP) + gidx + 1];
            }
            float s = 0.f, q = 0.f;
            float mx0 = -1e30f, mx1 = -1e30f;
            #pragma unroll
            for (int nt = 0; nt < 8; ++nt) {
                float h3v = (nt < 4) ? h3a : h3b;
                #pragma unroll
                for (int j = 0; j < 2; ++j) {
                    float v = acc[mt][nt][hf*2 + j] + h3v;
                    s += v; q = fmaf(v, v, q);
                    if (MODE == 1) {
                        int nl = wn*64 + nt*8 + qcol*2 + j;
                        st[nl*128 + mloc] = __float2half(v);
                    } else {
                        if (nt < 4) mx0 = fmaxf(mx0, v); else mx1 = fmaxf(mx1, v);
                    }
                }
            }
            if (MODE == 2) {
                mx0 = fmaxf(mx0, __shfl_xor_sync(0xffffffffu, mx0, 1));
                mx0 = fmaxf(mx0, __shfl_xor_sync(0xffffffffu, mx0, 2));
                mx1 = fmaxf(mx1, __shfl_xor_sync(0xffffffffu, mx1, 1));
                mx1 = fmaxf(mx1, __shfl_xor_sync(0xffffffffu, mx1, 2));
                if (qcol == 0) {
                    int bsg = (n0c >> 5) + wn*2;
                    g_y4m[mg*(BB*NSAMP) + bsg]     = mx0;
                    g_y4m[mg*(BB*NSAMP) + bsg + 1] = mx1;
                }
            }
            redS[mloc*16 + wn*4 + qcol] = s;
            redQ[mloc*16 + wn*4 + qcol] = q;
        }
    }
    __syncthreads();
    if (MODE == 1) {
        #pragma unroll
        for (int i = 0; i < 16; ++i) {
            int u = tid + i*256;
            int row = u >> 4, seg = u & 15;
            uint4 v = *(uint4*)(st + row*128 + seg*8);
            *(uint4*)(g_y3h + (size_t)(n0c + row)*512 + m0c + seg*8) = v;
        }
    }
    if (tid < 128) {
        float s = 0.f;
        #pragma unroll
        for (int i = 0; i < 16; ++i) s += redS[tid*16 + i];
        atomicAdd(&Su[m0c + tid], s);
    } else {
        int m = tid - 128;
        float q = 0.f;
        #pragma unroll
        for (int i = 0; i < 16; ++i) q += redQ[m*16 + i];
        atomicAdd(&Sq[m0c + m], q);
    }
}

// ---------------- fin2: out_feat = relu(aff4(y4max)) --------------------------
__global__ void k_fin2(float* __restrict__ out) {
    int c = blockIdx.x;        // 256
    int b = blockIdx.y;        // 4
    int s = threadIdx.x;       // 1024
    int bs = b*1024 + s;
    float v = g_y4m[c*(BB*NSAMP) + bs];
    float o = fmaxf(fmaf(v, g_s4[c], g_t4[c]), 0.f);
    out[(((b << 8) + c) << 10) + s] = o;
}

// ---------------- launcher ----------------------------------------------------
extern "C" void kernel_launch(void* const* d_in, const int* in_sizes, int n_in,
                              void* d_out, int out_size) {
    const float* p   = (const float*)d_in[0];
    const float* f   = (const float*)d_in[1];
    const float* w1  = (const float*)d_in[2];
    const float* w2  = (const float*)d_in[3];
    const float* b2  = (const float*)d_in[4];
    const float* g2  = (const float*)d_in[5];
    const float* be2 = (const float*)d_in[6];
    const float* w3  = (const float*)d_in[7];
    const float* g3  = (const float*)d_in[8];
    const float* be3 = (const float*)d_in[9];
    const float* w4  = (const float*)d_in[10];
    const float* g4  = (const float*)d_in[11];
    const float* be4 = (const float*)d_in[12];
    float* out = (float*)d_out;

    cudaFuncSetAttribute(k_mma<1>, cudaFuncAttributeMaxDynamicSharedMemorySize, MMA_SMEM);
    cudaFuncSetAttribute(k_mma<2>, cudaFuncAttributeMaxDynamicSharedMemorySize, MMA_SMEM);

    k_zero<<<1, 512>>>();
    k_w21<<<1, 256>>>(w1, w2);
    k_wsplit<<<512, 256>>>(w3, w4);
    k_fused<<<132, 512>>>(p, f, b2, out);              // fps + knn + gconv1 + stats2
    k_params<2><<<2, 256>>>(g2, be2);
    k_c1<<<BB*NSAMP, 256>>>();                         // y1a fp16 + xm
    k_gemm0<<<dim3(4, 32), 256>>>(w3);                 // h3 = w3a @ xm
    k_mma<1><<<dim3(4, 512), 256, MMA_SMEM>>>();       // y3h raw fp16 + stats3
    k_params<3><<<2, 256>>>(g3, be3);
    k_c3<<<65536, 256>>>();                            // y3a fp16
    k_mma<2><<<dim3(2, 512), 256, MMA_SMEM>>>();       // y4max + stats4
    k_params<4><<<2, 256>>>(g4, be4);
    k_fin2<<<dim3(256, 4), 1024>>>(out + BB*NSAMP*3);
}

// round 17
// speedup vs baseline: 1.2885x; 1.0170x over previous
#include <cuda_runtime.h>
#include <cuda_fp16.h>
#include <cstdint>

#define BB 4
#define NN 4096
#define NSAMP 1024
#define KNB 32
#define MTOT (BB*NSAMP*KNB)   // 131072 positions

// ---------------- scratch (device globals; no allocations allowed) ------------
__device__ float g_w21[256*6];
__device__ unsigned g_prog[4];                 // fps progress per batch
__device__ __half g_y1h[(size_t)MTOT*256];     // conv1 out RAW fp16, [m][c]
__device__ __half g_y1a[(size_t)MTOT*256];     // relu(aff2(y1)) fp16, [m][c]
__device__ float g_xm[256*BB*NSAMP];           // [c][bs]
__device__ float g_h3[512*BB*NSAMP];           // [row][bs]
__device__ __half g_y3h[(size_t)MTOT*512];     // conv3 out RAW fp16, [n][512]
__device__ __half g_y3a[(size_t)MTOT*512];     // relu(aff3(y3)) fp16
__device__ float g_y4m[256*BB*NSAMP];          // max_k of RAW y4, [c][bs]
__device__ __half g_w3bh[512*256];
__device__ __half g_w4h[256*512];
__device__ float g_sum2[256], g_sq2[256];
__device__ float g_sum3[512], g_sq3[512];
__device__ float g_sum4[256], g_sq4[256];
__device__ float g_s2[256], g_t2[256];
__device__ float g_s3[512], g_t3[512];
__device__ float g_s4[256], g_t4[256];

// ---------------- helpers -----------------------------------------------------
__device__ __forceinline__ uint32_t smem_to_u32(const void* p) {
    uint32_t a;
    asm("{ .reg .u64 t; cvta.to.shared.u64 t, %1; cvt.u32.u64 %0, t; }" : "=r"(a) : "l"(p));
    return a;
}
__device__ __forceinline__ unsigned long long dup2(float a) {
    unsigned int u = __float_as_uint(a);
    return ((unsigned long long)u << 32) | (unsigned long long)u;
}
__device__ __forceinline__ unsigned long long pk64(float a, float b) {
    unsigned long long r;
    asm("mov.b64 %0, {%1,%2};" : "=l"(r) : "f"(a), "f"(b));
    return r;
}
__device__ __forceinline__ void up64(float& a, float& b, unsigned long long v) {
    asm("mov.b64 {%0,%1}, %2;" : "=f"(a), "=f"(b) : "l"(v));
}
__device__ __forceinline__ unsigned long long fma2(unsigned long long a,
                                                   unsigned long long b,
                                                   unsigned long long c) {
    unsigned long long r;
    asm("fma.rn.f32x2 %0, %1, %2, %3;" : "=l"(r) : "l"(a), "l"(b), "l"(c));
    return r;
}
__device__ __forceinline__ unsigned int fmono(float f) {
    unsigned int u = __float_as_uint(f);
    return (u & 0x80000000u) ? ~u : (u | 0x80000000u);
}
__device__ __forceinline__ uint32_t pk2h(__half a, __half b) {
    return ((uint32_t)__half_as_ushort(b) << 16) | (uint32_t)__half_as_ushort(a);
}
__device__ __forceinline__ void st_rel(unsigned* p, unsigned v) {
    asm volatile("st.release.gpu.global.u32 [%0], %1;" :: "l"(p), "r"(v) : "memory");
}
__device__ __forceinline__ unsigned ld_acq(unsigned* p) {
    unsigned v;
    asm volatile("ld.acquire.gpu.global.u32 %0, [%1];" : "=r"(v) : "l"(p) : "memory");
    return v;
}
#define UBAR(id) asm volatile("bar.sync %0, 128;" :: "r"(id) : "memory")

#define CP_ASYNC16(dst, src) \
    asm volatile("cp.async.cg.shared.global [%0], [%1], 16;" :: "r"(dst), "l"(src) : "memory")
#define CP_COMMIT() asm volatile("cp.async.commit_group;" ::: "memory")
#define CP_WAIT0() asm volatile("cp.async.wait_group 0;" ::: "memory")
#define CP_WAIT1() asm volatile("cp.async.wait_group 1;" ::: "memory")

__device__ __forceinline__ void ldsm_x4(uint32_t& r0, uint32_t& r1, uint32_t& r2, uint32_t& r3, uint32_t addr) {
    asm volatile("ldmatrix.sync.aligned.m8n8.x4.shared.b16 {%0,%1,%2,%3}, [%4];"
        : "=r"(r0), "=r"(r1), "=r"(r2), "=r"(r3) : "r"(addr));
}
__device__ __forceinline__ void ldsm_x2(uint32_t& r0, uint32_t& r1, uint32_t addr) {
    asm volatile("ldmatrix.sync.aligned.m8n8.x2.shared.b16 {%0,%1}, [%2];"
        : "=r"(r0), "=r"(r1) : "r"(addr));
}
__device__ __forceinline__ void mma16816(float* d, const uint32_t* a, const uint32_t* b) {
    asm volatile("mma.sync.aligned.m16n8k16.row.col.f32.f16.f16.f32 "
        "{%0,%1,%2,%3}, {%4,%5,%6,%7}, {%8,%9}, {%0,%1,%2,%3};"
        : "+f"(d[0]), "+f"(d[1]), "+f"(d[2]), "+f"(d[3])
        : "r"(a[0]), "r"(a[1]), "r"(a[2]), "r"(a[3]), "r"(b[0]), "r"(b[1]));
}

// ---------------- zero stats + progress ---------------------------------------
__global__ void k_zero() {
    int t = threadIdx.x;  // 512
    if (t < 256) { g_sum2[t]=0.f; g_sq2[t]=0.f; g_sum4[t]=0.f; g_sq4[t]=0.f; }
    g_sum3[t]=0.f; g_sq3[t]=0.f;
    if (t < 4) g_prog[t] = 0u;
}

// ---------------- w21 = w2 @ w1 -----------------------------------------------
__global__ void k_w21(const float* __restrict__ w1, const float* __restrict__ w2) {
    int o = threadIdx.x;
    float acc[6] = {0.f,0.f,0.f,0.f,0.f,0.f};
    for (int c = 0; c < 256; ++c) {
        float w = w2[o*256 + c];
        #pragma unroll
        for (int i = 0; i < 6; ++i) acc[i] = fmaf(w, w1[c*6+i], acc[i]);
    }
    #pragma unroll
    for (int i = 0; i < 6; ++i) g_w21[o*6+i] = acc[i];
}

// ---------------- weight fp16 -------------------------------------------------
__global__ void k_wsplit(const float* __restrict__ w3, const float* __restrict__ w4) {
    int i = blockIdx.x*256 + threadIdx.x;   // 0..131071
    int r = i >> 8, c = i & 255;
    g_w3bh[i] = __float2half(w3[r*512 + 256 + c]);
    g_w4h[i]  = __float2half(w4[i]);
}

// ======== FUSED: fps producers (blocks 0-3) + knn/gconv1 consumers ============
// 132 blocks x 512 thr, single wave. Producer publishes progress every 16
// centroids. Consumer knn uses candidate caching: after the initial full scan,
// only the round winner rescans (selection order provably identical).
__global__ void __launch_bounds__(512, 1) k_fused(const float* __restrict__ p,
                                                  const float* __restrict__ f,
                                                  const float* __restrict__ b2,
                                                  float* __restrict__ outC) {
    int t = threadIdx.x;

    if (blockIdx.x < 4) {
        // ------------------------- FPS producer -------------------------------
        __shared__ unsigned s_v[2][16];
        __shared__ unsigned s_i[2][16];
        int b = blockIdx.x;
        const float* pb = p + b*NN*3;
        int lane = t & 31, w = t >> 5;

        float dm[8];
        unsigned long long pX[4], pY[4], pZ[4];
        #pragma unroll
        for (int j = 0; j < 4; ++j) {
            int i0 = t + (2*j)*512, i1 = t + (2*j+1)*512;
            pX[j] = pk64(pb[i0*3],   pb[i1*3]);
            pY[j] = pk64(pb[i0*3+1], pb[i1*3+1]);
            pZ[j] = pk64(pb[i0*3+2], pb[i1*3+2]);
            dm[2*j] = 1e10f; dm[2*j+1] = 1e10f;
        }
        const unsigned long long NEG1 = dup2(-1.0f);

        float cx = pb[0], cy = pb[1], cz = pb[2];
        if (t == 0) {
            float* o = outC + b*NSAMP*3;
            o[0] = cx; o[1] = cy; o[2] = cz;
            st_rel(&g_prog[b], 1u);
        }

        for (int it = 0; it < NSAMP; ++it) {
            int buf = it & 1;
            unsigned long long c2x = dup2(cx), c2y = dup2(cy), c2z = dup2(cz);
            #pragma unroll
            for (int j = 0; j < 4; ++j) {
                unsigned long long tx = fma2(c2x, NEG1, pX[j]);
                unsigned long long ty = fma2(c2y, NEG1, pY[j]);
                unsigned long long tz = fma2(c2z, NEG1, pZ[j]);
                unsigned long long d2 = fma2(tx, tx, 0ull);
                d2 = fma2(ty, ty, d2);
                d2 = fma2(tz, tz, d2);
                float da, db; up64(da, db, d2);
                dm[2*j]   = fminf(dm[2*j],   da);
                dm[2*j+1] = fminf(dm[2*j+1], db);
            }

            float best = dm[0];
            #pragma unroll
            for (int j = 1; j < 8; ++j) best = fmaxf(best, dm[j]);
            int bi = t + 7*512;
            #pragma unroll
            for (int j = 6; j >= 0; --j) if (dm[j] == best) bi = t + j*512;

            unsigned mv   = fmono(best);
            unsigned wmax = __reduce_max_sync(0xffffffffu, mv);
            unsigned cand = (mv == wmax) ? (unsigned)bi : 0xffffffffu;
            unsigned widx = __reduce_min_sync(0xffffffffu, cand);
            if (lane == 0) { s_v[buf][w] = wmax; s_i[buf][w] = widx; }
            __syncthreads();

            unsigned mv2 = (lane < 16) ? s_v[buf][lane] : 0u;
            unsigned id2 = (lane < 16) ? s_i[buf][lane] : 0xffffffffu;
            unsigned m2  = __reduce_max_sync(0xffffffffu, mv2);
            unsigned c2v = (mv2 == m2) ? id2 : 0xffffffffu;
            unsigned far = __reduce_min_sync(0xffffffffu, c2v);

            cx = pb[far*3]; cy = pb[far*3+1]; cz = pb[far*3+2];
            if (t == 0 && it + 1 < NSAMP) {
                float* o = outC + (b*NSAMP + it + 1)*3;
                o[0] = cx; o[1] = cy; o[2] = cz;
                if (((it + 2) & 15) == 0)                 // 64 fences total
                    st_rel(&g_prog[b], (unsigned)(it + 2));
            }
        }
    } else {
        // ------------------- consumer: 4 x 128-thread knn units ----------------
        __shared__ float sw[1536];
        __shared__ float sbb[256];
        __shared__ float sv4[4][32][6];
        __shared__ int   sidx4[4][32];
        __shared__ unsigned sh4[4][2][4], sl4[4][2][4];

        for (int i = t; i < 1536; i += 512) sw[i] = g_w21[i];
        if (t < 256) sbb[t] = b2[t];
        __syncthreads();

        int su = t >> 7;            // unit 0..3 == batch
        int tl = t & 127;           // local thread within unit
        int wl = tl >> 5, lane = t & 31;
        int cb = blockIdx.x - 4;    // 0..127
        int b = su;
        const float* pb = p + b*NN*3;
        const float* fb = f + b*3*NN;
        int bar = su + 1;

        int c0 = tl, c1 = tl + 128;
        float wA0=sw[c0*6],wA1=sw[c0*6+1],wA2=sw[c0*6+2];
        float wA3=sw[c0*6+3],wA4=sw[c0*6+4],wA5=sw[c0*6+5];
        float wB0=sw[c1*6],wB1=sw[c1*6+1],wB2=sw[c1*6+2];
        float wB3=sw[c1*6+3],wB4=sw[c1*6+4],wB5=sw[c1*6+5];
        float bias0 = sbb[c0], bias1 = sbb[c1];
        float s0=0.f,q0=0.f,s1=0.f,q1=0.f;

        for (int g = 0; g < 8; ++g) {
            int sI = g*128 + cb;
            int cid = b*1024 + sI;

            if (tl == 0) {
                while ((int)ld_acq(&g_prog[b]) <= sI) __nanosleep(256);
            }
            UBAR(bar);

            float cx = __ldcg(outC + cid*3);
            float cy = __ldcg(outC + cid*3 + 1);
            float cz = __ldcg(outC + cid*3 + 2);
            float cn = cx*cx + cy*cy + cz*cz;

            unsigned long long key[32];
            #pragma unroll
            for (int j = 0; j < 32; ++j) {
                int i = j*128 + tl;
                float x = pb[i*3], y = pb[i*3+1], z = pb[i*3+2];
                float pn = x*x + y*y + z*z;
                float dot = fmaf(cx, x, fmaf(cy, y, cz*z));
                float d2  = fmaf(-2.0f, dot, cn + pn);
                key[j] = ((unsigned long long)fmono(d2) << 32) | (unsigned int)i;
            }

            // initial candidate = min over all keys (all keys > 0)
            unsigned long long cand;
            {
                unsigned long long b0 = key[0], b1 = key[8], b2k = key[16], b3 = key[24];
                #pragma unroll
                for (int j = 1; j < 8; ++j) {
                    if (key[j]      < b0)  b0  = key[j];
                    if (key[8 + j]  < b1)  b1  = key[8 + j];
                    if (key[16 + j] < b2k) b2k = key[16 + j];
                    if (key[24 + j] < b3)  b3  = key[24 + j];
                }
                if (b1 < b0) b0 = b1;
                if (b3 < b2k) b2k = b3;
                cand = (b2k < b0) ? b2k : b0;
            }

            for (int r = 0; r < KNB; ++r) {
                int rb = r & 1;
                unsigned bh = (unsigned)(cand >> 32), bl = (unsigned)cand;
                unsigned mh = __reduce_min_sync(0xffffffffu, bh);
                unsigned cl = (bh == mh) ? bl : 0xffffffffu;
                unsigned ml = __reduce_min_sync(0xffffffffu, cl);
                if (lane == 0) { sh4[su][rb][wl] = mh; sl4[su][rb][wl] = ml; }
                UBAR(bar);

                unsigned fh = sh4[su][rb][0], fl = sl4[su][rb][0];
                #pragma unroll
                for (int i = 1; i < 4; ++i) {
                    unsigned hh = sh4[su][rb][i], ll = sl4[su][rb][i];
                    if (hh < fh || (hh == fh && ll < fl)) { fh = hh; fl = ll; }
                }
                unsigned long long prev = ((unsigned long long)fh << 32) | fl;
                if (tl == 0) sidx4[su][r] = (int)fl;

                // only the winner's candidate is invalidated -> rescan
                if (cand == prev) {
                    unsigned long long b0 = ~0ull, b1 = ~0ull, b2k = ~0ull, b3 = ~0ull;
                    #pragma unroll
                    for (int j = 0; j < 8; ++j) {
                        unsigned long long k0 = key[j];
                        if (k0 > prev && k0 < b0) b0 = k0;
                        unsigned long long k1 = key[8 + j];
                        if (k1 > prev && k1 < b1) b1 = k1;
                        unsigned long long k2 = key[16 + j];
                        if (k2 > prev && k2 < b2k) b2k = k2;
                        unsigned long long k3 = key[24 + j];
                        if (k3 > prev && k3 < b3) b3 = k3;
                    }
                    if (b1 < b0) b0 = b1;
                    if (b3 < b2k) b2k = b3;
                    cand = (b2k < b0) ? b2k : b0;
                }
            }
            UBAR(bar);                      // sidx writes visible

            if (tl < 32) {
                int idx = sidx4[su][tl];
                const float* pp = pb + idx*3;
                sv4[su][tl][0] = pp[0]; sv4[su][tl][1] = pp[1]; sv4[su][tl][2] = pp[2];
                sv4[su][tl][3] = fb[idx]; sv4[su][tl][4] = fb[NN + idx];
                sv4[su][tl][5] = fb[2*NN + idx];
            }
            UBAR(bar);

            size_t mbase = (size_t)cid*32;
            #pragma unroll 4
            for (int pp = 0; pp < 32; ++pp) {
                float v0 = sv4[su][pp][0], v1 = sv4[su][pp][1], v2 = sv4[su][pp][2];
                float v3 = sv4[su][pp][3], v4 = sv4[su][pp][4], v5 = sv4[su][pp][5];
                float a0 = bias0;
                a0 = fmaf(wA0, v0, a0); a0 = fmaf(wA1, v1, a0); a0 = fmaf(wA2, v2, a0);
                a0 = fmaf(wA3, v3, a0); a0 = fmaf(wA4, v4, a0); a0 = fmaf(wA5, v5, a0);
                float a1 = bias1;
                a1 = fmaf(wB0, v0, a1); a1 = fmaf(wB1, v1, a1); a1 = fmaf(wB2, v2, a1);
                a1 = fmaf(wB3, v3, a1); a1 = fmaf(wB4, v4, a1); a1 = fmaf(wB5, v5, a1);
                g_y1h[(mbase + pp)*256 + c0] = __float2half(a0);
                g_y1h[(mbase + pp)*256 + c1] = __float2half(a1);
                s0 += a0; q0 = fmaf(a0, a0, q0);
                s1 += a1; q1 = fmaf(a1, a1, q1);
            }
            UBAR(bar);                      // protect sv4/sidx4 for next centroid
        }
        atomicAdd(&g_sum2[c0], s0); atomicAdd(&g_sq2[c0], q0);
        atomicAdd(&g_sum2[c1], s1); atomicAdd(&g_sq2[c1], q1);
    }
}

// ---------------- BN params ---------------------------------------------------
template<int STAGE>
__global__ void k_params(const float* __restrict__ g, const float* __restrict__ be) {
    constexpr int C = (STAGE == 3) ? 512 : 256;
    const float* su = (STAGE == 2) ? g_sum2 : (STAGE == 3) ? g_sum3 : g_sum4;
    const float* sq = (STAGE == 2) ? g_sq2  : (STAGE == 3) ? g_sq3  : g_sq4;
    float* sc = (STAGE == 2) ? g_s2 : (STAGE == 3) ? g_s3 : g_s4;
    float* sh = (STAGE == 2) ? g_t2 : (STAGE == 3) ? g_t3 : g_t4;
    int c = blockIdx.x*blockDim.x + threadIdx.x;
    if (c < C) {
        const float inv = 1.0f / (float)MTOT;
        float mean = su[c]*inv;
        float var  = fmaf(-mean, mean, sq[c]*inv);
        float r    = rsqrtf(var + 1e-5f);
        float s    = g[c]*r;
        sc[c] = s;
        sh[c] = fmaf(-mean, s, be[c]);
    }
}

// ---- c1: relu(aff2(y1h)) -> fp16 [m][256] + xm [c][bs] -----------------------
__global__ void k_c1() {
    int bs = blockIdx.x;      // 4096
    int c  = threadIdx.x;     // 256
    float sc = g_s2[c], hh = g_t2[c];
    size_t base = (size_t)bs*32*256 + c;
    float mx = 0.f;
    #pragma unroll 8
    for (int pp = 0; pp < 32; ++pp) {
        float v = __half2float(g_y1h[base + (size_t)pp*256]);
        float a = fmaxf(fmaf(v, sc, hh), 0.f);
        mx = fmaxf(mx, a);
        g_y1a[base + (size_t)pp*256] = __float2half(a);
    }
    g_xm[c*(BB*NSAMP) + bs] = mx;
}

// ---- c3: relu(aff3(y3h)) -> fp16 [n][512] ------------------------------------
__global__ void k_c3() {
    size_t i = (size_t)blockIdx.x*256 + threadIdx.x;   // uint2 index (16.7M)
    uint2 r = ((const uint2*)g_y3h)[i];
    int k = ((int)(i & 127)) * 4;
    __half2 v01 = *(__half2*)&r.x;
    __half2 v23 = *(__half2*)&r.y;
    float a0 = fmaxf(fmaf(__low2float(v01),  g_s3[k],   g_t3[k]),   0.f);
    float a1 = fmaxf(fmaf(__high2float(v01), g_s3[k+1], g_t3[k+1]), 0.f);
    float a2 = fmaxf(fmaf(__low2float(v23),  g_s3[k+2], g_t3[k+2]), 0.f);
    float a3 = fmaxf(fmaf(__high2float(v23), g_s3[k+3], g_t3[k+3]), 0.f);
    ((uint2*)g_y3a)[i] = make_uint2(pk2h(__float2half(a0), __float2half(a1)),
                                   pk2h(__float2half(a2), __float2half(a3)));
}

// ---------------- small fp32 GEMM: h3 = w3[:, :256] @ xm ----------------------
__global__ void __launch_bounds__(256, 2) k_gemm0(const float* __restrict__ A) {
    constexpr int Nn = BB*NSAMP;     // 4096
    constexpr int Kd = 256, lda = 512;
    __shared__ unsigned long long As[16][128];
    __shared__ float Bs[16][128];
    int m0 = blockIdx.x * 128;
    int n0 = blockIdx.y * 128;
    int t  = threadIdx.x;
    int ar  = t & 127, akq = (t >> 7) * 8;
    int bkr = t >> 4,  bnc = (t & 15) * 8;
    int ty = t >> 4, tx = t & 15;
    unsigned long long acc[8][4];
    #pragma unroll
    for (int i = 0; i < 8; ++i)
        #pragma unroll
        for (int j = 0; j < 4; ++j) acc[i][j] = 0ull;
    for (int k0 = 0; k0 < Kd; k0 += 16) {
        const float* ga = A + (size_t)(m0 + ar)*lda + k0 + akq;
        float4 a0 = *(const float4*)ga;
        float4 a1 = *(const float4*)(ga + 4);
        const float* gb = g_xm + (size_t)(k0 + bkr)*Nn + n0 + bnc;
        float4 b0 = *(const float4*)gb;
        float4 b1 = *(const float4*)(gb + 4);
        __syncthreads();
        As[akq+0][ar] = dup2(a0.x); As[akq+1][ar] = dup2(a0.y);
        As[akq+2][ar] = dup2(a0.z); As[akq+3][ar] = dup2(a0.w);
        As[akq+4][ar] = dup2(a1.x); As[akq+5][ar] = dup2(a1.y);
        As[akq+6][ar] = dup2(a1.z); As[akq+7][ar] = dup2(a1.w);
        *(float4*)&Bs[bkr][bnc]     = b0;
        *(float4*)&Bs[bkr][bnc + 4] = b1;
        __syncthreads();
        #pragma unroll
        for (int kk = 0; kk < 16; ++kk) {
            unsigned long long af[8], bf[4];
            const unsigned long long* ap = &As[kk][ty*8];
            #pragma unroll
            for (int i = 0; i < 8; ++i) af[i] = ap[i];
            const unsigned long long* bp = (const unsigned long long*)&Bs[kk][tx*8];
            #pragma unroll
            for (int j = 0; j < 4; ++j) bf[j] = bp[j];
            #pragma unroll
            for (int i = 0; i < 8; ++i)
                #pragma unroll
                for (int j = 0; j < 4; ++j)
                    asm("fma.rn.f32x2 %0, %1, %2, %0;"
                        : "+l"(acc[i][j]) : "l"(af[i]), "l"(bf[j]));
        }
    }
    #pragma unroll
    for (int i = 0; i < 8; ++i) {
        int gr = m0 + ty*8 + i;
        float out[8];
        #pragma unroll
        for (int j = 0; j < 4; ++j) {
            out[2*j]   = __uint_as_float((unsigned int)(acc[i][j] & 0xffffffffull));
            out[2*j+1] = __uint_as_float((unsigned int)(acc[i][j] >> 32));
        }
        float4* cp = (float4*)(g_h3 + (size_t)gr*Nn + n0 + tx*8);
        cp[0] = make_float4(out[0], out[1], out[2], out[3]);
        cp[1] = make_float4(out[4], out[5], out[6], out[7]);
    }
}

// ---------------- mma.sync fp16 GEMM (single pass), CTA 128x256 ---------------
// MODE 1: y3h[n][512] = fp16(w3b @ y1a^T + h3), stats3   (smem-transposed store)
// MODE 2: y4max[c][bs] = max_k (w4 @ y3a^T), stats4      (no bulk store)
#define STG_BYTES 30720
#define MMA_SMEM  92160

template<int MODE>
__device__ __forceinline__ void mma_issue(uint32_t sbase, int st, int k0,
                                          int m0c, int n0c, int tid) {
    constexpr int Kd = (MODE == 1) ? 256 : 512;
    const __half* __restrict__ Ah = (MODE == 1) ? g_w3bh : g_w4h;
    const __half* __restrict__ Bh = (MODE == 1) ? g_y1a : g_y3a;
    uint32_t base = sbase + st*STG_BYTES;
    #pragma unroll
    for (int i = 0; i < 2; ++i) {
        int u = tid + i*256;
        int r = u >> 2, q = u & 3;
        const __half* src = Ah + (size_t)(m0c + r)*Kd + k0 + q*8;
        CP_ASYNC16(base + r*80 + q*16, src);
    }
    #pragma unroll
    for (int i = 0; i < 4; ++i) {
        int u = tid + i*256;
        int r = u >> 2, q = u & 3;
        const __half* src = Bh + (size_t)(n0c + r)*Kd + k0 + q*8;
        CP_ASYNC16(base + 10240 + r*80 + q*16, src);
    }
}

template<int MODE>
__global__ void __launch_bounds__(256) k_mma() {
    constexpr int Kd = (MODE == 1) ? 256 : 512;
    constexpr int KT = Kd / 32;
    float* __restrict__ Su = (MODE == 1) ? g_sum3 : g_sum4;
    float* __restrict__ Sq = (MODE == 1) ? g_sq3 : g_sq4;

    extern __shared__ char smem[];
    uint32_t sb = smem_to_u32(smem);
    int tid = threadIdx.x, lane = tid & 31, wid = tid >> 5;
    int wm = wid >> 2, wn = wid & 3;
    int m0c = blockIdx.x * 128, n0c = blockIdx.y * 256;

    float acc[4][8][4];
    #pragma unroll
    for (int a = 0; a < 4; ++a)
        #pragma unroll
        for (int b = 0; b < 8; ++b)
            #pragma unroll
            for (int c = 0; c < 4; ++c) acc[a][b][c] = 0.f;

    int sel = lane >> 3;
    uint32_t aRow = (uint32_t)((sel & 1)*8 + (lane & 7));
    uint32_t aCol = (uint32_t)((sel >> 1) * 16);
    uint32_t bRowB = (uint32_t)(wn*64 + (lane & 7));
    uint32_t bCol = (uint32_t)(((lane >> 3) & 1) * 16);

    mma_issue<MODE>(sb, 0, 0,  m0c, n0c, tid); CP_COMMIT();
    mma_issue<MODE>(sb, 1, 32, m0c, n0c, tid); CP_COMMIT();

    for (int kt = 0; kt < KT; ++kt) {
        if (kt == KT-1) { CP_WAIT0(); } else { CP_WAIT1(); }
        __syncthreads();
        if (kt + 2 < KT) {
            mma_issue<MODE>(sb, (kt+2)%3, (kt+2)*32, m0c, n0c, tid);
            CP_COMMIT();
        }
        uint32_t sA = sb + (kt%3)*STG_BYTES;
        uint32_t sBB = sA + 10240;
        #pragma unroll
        for (int ks = 0; ks < 2; ++ks) {
            uint32_t kOff = (uint32_t)(ks*32);
            uint32_t ah[4][4], bf[8][2];
            #pragma unroll
            for (int mt = 0; mt < 4; ++mt)
                ldsm_x4(ah[mt][0], ah[mt][1], ah[mt][2], ah[mt][3],
                        sA + (uint32_t)(wm*64 + mt*16 + aRow)*80 + kOff + aCol);
            #pragma unroll
            for (int nt = 0; nt < 8; ++nt)
                ldsm_x2(bf[nt][0], bf[nt][1],
                        sBB + (bRowB + (uint32_t)(nt*8))*80 + kOff + bCol);
            #pragma unroll
            for (int mt = 0; mt < 4; ++mt)
                #pragma unroll
                for (int nt = 0; nt < 8; ++nt)
                    mma16816(acc[mt][nt], ah[mt], bf[nt]);
        }
    }

    // ---------------- epilogue ------------------------------------------------
    __syncthreads();
    __half* st = (__half*)smem;              // 256 x 128 halves (64KB), MODE 1
    float* redS = (float*)(smem + 65536);    // [128][16]
    float* redQ = (float*)(smem + 73728);
    int qrow = lane >> 2, qcol = lane & 3;

    #pragma unroll
    for (int mt = 0; mt < 4; ++mt) {
        #pragma unroll
        for (int hf = 0; hf < 2; ++hf) {
            int mloc = wm*64 + mt*16 + hf*8 + qrow;
            int mg = m0c + mloc;
            float h3a = 0.f, h3b = 0.f;
            if (MODE == 1) {
                int gidx = (n0c >> 5) + wn*2;
                h3a = g_h3[(size_t)mg*(BB*NSAMP) + gidx];
                h3b = g_h3[(size_t)mg*(BB*NSAMP) + gidx + 1];
            }
            float s = 0.f, q = 0.f;
            float mx0 = -1e30f, mx1 = -1e30f;
            #pragma unroll
            for (int nt = 0; nt < 8; ++nt) {
                float h3v = (nt < 4) ? h3a : h3b;
                #pragma unroll
                for (int j = 0; j < 2; ++j) {
                    float v = acc[mt][nt][hf*2 + j] + h3v;
                    s += v; q = fmaf(v, v, q);
                    if (MODE == 1) {
                        int nl = wn*64 + nt*8 + qcol*2 + j;
                        st[nl*128 + mloc] = __float2half(v);
                    } else {
                        if (nt < 4) mx0 = fmaxf(mx0, v); else mx1 = fmaxf(mx1, v);
                    }
                }
            }
            if (MODE == 2) {
                mx0 = fmaxf(mx0, __shfl_xor_sync(0xffffffffu, mx0, 1));
                mx0 = fmaxf(mx0, __shfl_xor_sync(0xffffffffu, mx0, 2));
                mx1 = fmaxf(mx1, __shfl_xor_sync(0xffffffffu, mx1, 1));
                mx1 = fmaxf(mx1, __shfl_xor_sync(0xffffffffu, mx1, 2));
                if (qcol == 0) {
                    int bsg = (n0c >> 5) + wn*2;
                    g_y4m[mg*(BB*NSAMP) + bsg]     = mx0;
                    g_y4m[mg*(BB*NSAMP) + bsg + 1] = mx1;
                }
            }
            redS[mloc*16 + wn*4 + qcol] = s;
            redQ[mloc*16 + wn*4 + qcol] = q;
        }
    }
    __syncthreads();
    if (MODE == 1) {
        #pragma unroll
        for (int i = 0; i < 16; ++i) {
            int u = tid + i*256;
            int row = u >> 4, seg = u & 15;
            uint4 v = *(uint4*)(st + row*128 + seg*8);
            *(uint4*)(g_y3h + (size_t)(n0c + row)*512 + m0c + seg*8) = v;
        }
    }
    if (tid < 128) {
        float s = 0.f;
        #pragma unroll
        for (int i = 0; i < 16; ++i) s += redS[tid*16 + i];
        atomicAdd(&Su[m0c + tid], s);
    } else {
        int m = tid - 128;
        float q = 0.f;
        #pragma unroll
        for (int i = 0; i < 16; ++i) q += redQ[m*16 + i];
        atomicAdd(&Sq[m0c + m], q);
    }
}

// ---------------- fin2: out_feat = relu(aff4(y4max)) --------------------------
__global__ void k_fin2(float* __restrict__ out) {
    int c = blockIdx.x;        // 256
    int b = blockIdx.y;        // 4
    int s = threadIdx.x;       // 1024
    int bs = b*1024 + s;
    float v = g_y4m[c*(BB*NSAMP) + bs];
    float o = fmaxf(fmaf(v, g_s4[c], g_t4[c]), 0.f);
    out[(((b << 8) + c) << 10) + s] = o;
}

// ---------------- launcher ----------------------------------------------------
extern "C" void kernel_launch(void* const* d_in, const int* in_sizes, int n_in,
                              void* d_out, int out_size) {
    const float* p   = (const float*)d_in[0];
    const float* f   = (const float*)d_in[1];
    const float* w1  = (const float*)d_in[2];
    const float* w2  = (const float*)d_in[3];
    const float* b2  = (const float*)d_in[4];
    const float* g2  = (const float*)d_in[5];
    const float* be2 = (const float*)d_in[6];
    const float* w3  = (const float*)d_in[7];
    const float* g3  = (const float*)d_in[8];
    const float* be3 = (const float*)d_in[9];
    const float* w4  = (const float*)d_in[10];
    const float* g4  = (const float*)d_in[11];
    const float* be4 = (const float*)d_in[12];
    float* out = (float*)d_out;

    cudaFuncSetAttribute(k_mma<1>, cudaFuncAttributeMaxDynamicSharedMemorySize, MMA_SMEM);
    cudaFuncSetAttribute(k_mma<2>, cudaFuncAttributeMaxDynamicSharedMemorySize, MMA_SMEM);

    k_zero<<<1, 512>>>();
    k_w21<<<1, 256>>>(w1, w2);
    k_wsplit<<<512, 256>>>(w3, w4);
    k_fused<<<132, 512>>>(p, f, b2, out);              // fps + knn + gconv1 + stats2
    k_params<2><<<2, 256>>>(g2, be2);
    k_c1<<<BB*NSAMP, 256>>>();                         // y1a fp16 + xm
    k_gemm0<<<dim3(4, 32), 256>>>(w3);                 // h3 = w3a @ xm
    k_mma<1><<<dim3(4, 512), 256, MMA_SMEM>>>();       // y3h raw fp16 + stats3
    k_params<3><<<2, 256>>>(g3, be3);
    k_c3<<<65536, 256>>>();                            // y3a fp16
    k_mma<2><<<dim3(2, 512), 256, MMA_SMEM>>>();       // y4max + stats4
    k_params<4><<<2, 256>>>(g4, be4);
    k_fin2<<<dim3(256, 4), 1024>>>(out + BB*NSAMP*3);
}